// round 17
// baseline (speedup 1.0000x reference)
#include <cuda_runtime.h>
#include <cuda_fp16.h>
#include <cstdint>

// ============================================================================
// CKAN layer == single GEMM: out[c,p] = W[128,6912] @ F[6912,8192]
//   k = s*12 + j ; j=0 -> silu(u[s,p]) * base_w ; j>0 -> basis_j(u) * sw*coeff
// F built on the fly in SMEM. W packed fp16 in __device__ global.
// mma.sync.m16n8k16 (plain-sm_103 target; tcgen05 PTX rejected by harness).
//
// v8 (resubmit after infra failure; barrier audit clean):
//   - 384 thr: warps 0-7 consumers (32x32 tiles), 8-11 producers
//   - producer x-loads pipelined across ring stages (LDG overlaps EMPTY-wait)
//   - named-barrier FULL/EMPTY ring depth 2 (populations 384)
// K-split x4 + deterministic reduce kept.
// ============================================================================
static constexpr int SIZE_S  = 576;
static constexpr int NFEAT   = 12;
static constexpr int K_TOTAL = SIZE_S * NFEAT;   // 6912
static constexpr int OUT_CH  = 128;
static constexpr int KC      = 48;               // K per chunk = 4 s * 12
static constexpr int NSPLIT  = 4;
static constexpr int NIT_S   = K_TOTAL / KC / NSPLIT;  // 36 iters per split
static constexpr int SA      = 56;               // A row stride (halves)
static constexpr int SB      = 72;               // B row stride (halves)
static constexpr int A_HALVES = 128 * SA;        // 7168 per buffer (14336 B)
static constexpr int B_HALVES = KC * SB;         // 3456 per buffer ( 6912 B)
static constexpr int NTHR    = 384;

__device__ __half g_W[(size_t)OUT_CH * K_TOTAL];            // 1.77 MB
__device__ float  g_P[(size_t)NSPLIT * OUT_CH * 8192];      // 16 MB partials

#define BAR_FULL(b)  (1 + (b))
#define BAR_EMPTY(b) (3 + (b))

// ---------------------------------------------------------------------------
__device__ __forceinline__ uint32_t smem_u32(const void* p) {
    uint32_t a;
    asm("{ .reg .u64 t; cvta.to.shared.u64 t, %1; cvt.u32.u64 %0, t; }"
        : "=r"(a) : "l"(p));
    return a;
}
__device__ __forceinline__ void bar_sync(int id) {
    asm volatile("bar.sync %0, %1;" :: "r"(id), "n"(NTHR) : "memory");
}
__device__ __forceinline__ void bar_arrive(int id) {
    asm volatile("bar.arrive %0, %1;" :: "r"(id), "n"(NTHR) : "memory");
}
__device__ __forceinline__ void cp_async16(uint32_t dst, const void* src) {
    asm volatile("cp.async.cg.shared.global [%0], [%1], 16;"
                 :: "r"(dst), "l"(src));
}
__device__ __forceinline__ void cp_commit() {
    asm volatile("cp.async.commit_group;");
}
__device__ __forceinline__ void cp_wait0() {
    asm volatile("cp.async.wait_group 0;");
}
__device__ __forceinline__ void ldsm_x4(uint32_t* r, uint32_t addr) {
    asm volatile("ldmatrix.sync.aligned.m8n8.x4.shared.b16 {%0,%1,%2,%3}, [%4];"
        : "=r"(r[0]), "=r"(r[1]), "=r"(r[2]), "=r"(r[3]) : "r"(addr));
}
__device__ __forceinline__ void ldsm_x4_t(uint32_t* r, uint32_t addr) {
    asm volatile("ldmatrix.sync.aligned.m8n8.x4.trans.shared.b16 {%0,%1,%2,%3}, [%4];"
        : "=r"(r[0]), "=r"(r[1]), "=r"(r[2]), "=r"(r[3]) : "r"(addr));
}
__device__ __forceinline__ void mma16816(float* d, const uint32_t* a,
                                         const uint32_t* b) {
    asm volatile(
        "mma.sync.aligned.m16n8k16.row.col.f32.f16.f16.f32 "
        "{%0,%1,%2,%3}, {%4,%5,%6,%7}, {%8,%9}, {%0,%1,%2,%3};"
        : "+f"(d[0]), "+f"(d[1]), "+f"(d[2]), "+f"(d[3])
        : "r"(a[0]), "r"(a[1]), "r"(a[2]), "r"(a[3]), "r"(b[0]), "r"(b[1]));
}

// ============================================================================
// Kernel 1: pack W[c,k] fp16
// ============================================================================
__global__ void build_w_kernel(const float* __restrict__ coeff,
                               const float* __restrict__ bw,
                               const float* __restrict__ sw) {
    int idx = blockIdx.x * blockDim.x + threadIdx.x;
    if (idx >= OUT_CH * K_TOTAL) return;
    int c = idx / K_TOTAL;
    int r = idx - c * K_TOTAL;
    int s = r / NFEAT;
    int j = r - s * NFEAT;
    int cs = c * SIZE_S + s;
    float v = (j == 0) ? bw[cs] : sw[cs] * coeff[cs * 11 + (j - 1)];
    g_W[idx] = __float2half(v);
}

// ============================================================================
// Producer helpers (warps 8-11, t2 = tid-256 in [0,128))
// ============================================================================
__device__ __forceinline__ void feat_load(
    const float* __restrict__ x, int g, int t2, int poff, int n_img,
    float& v0, float& v1)
{
    int s_local = t2 >> 5;
    int pp      = (t2 & 31) * 2;
    int s   = g * 4 + s_local;
    int cin = s / 9;
    int kk  = s - cin * 9;
    int dy  = kk / 3 - 1;
    int dx  = kk - (kk / 3) * 3 - 1;
    const float* xc = x + (((size_t)n_img * 64 + cin) << 10);

    int gp0 = poff + pp;
    int iy0 = (gp0 >> 5) + dy, ix0 = (gp0 & 31) + dx;
    int iy1 = ((gp0 + 1) >> 5) + dy, ix1 = ((gp0 + 1) & 31) + dx;
    v0 = 0.0f; v1 = 0.0f;
    if (iy0 >= 0 && iy0 < 32 && ix0 >= 0 && ix0 < 32)
        v0 = __ldg(xc + (iy0 << 5) + ix0);
    if (iy1 >= 0 && iy1 < 32 && ix1 >= 0 && ix1 < 32)
        v1 = __ldg(xc + (iy1 << 5) + ix1);
}

__device__ __forceinline__ void feat_store(
    float v0, float v1, __half* __restrict__ sBb, int t2)
{
    int s_local = t2 >> 5;
    int pp      = (t2 & 31) * 2;
    float vv[2] = {v0, v1};
    float f2[2][NFEAT];
    #pragma unroll
    for (int q = 0; q < 2; q++) {
        float v = vv[q];
        f2[q][0] = v / (1.0f + __expf(-v));
        #pragma unroll
        for (int j = 1; j < NFEAT; j++) f2[q][j] = 0.0f;
        float tp = (v + 1.75f) * 4.0f;
        if (tp >= 0.0f && tp < 14.0f) {
            int m = (int)tp;
            float t = tp - (float)m, omt = 1.0f - t;
            float t2f = t * t, t3 = t2f * t;
            float b0 = omt * omt * omt * (1.0f / 6.0f);
            float b1 = (3.0f * t3 - 6.0f * t2f + 4.0f) * (1.0f / 6.0f);
            float b2 = (-3.0f * t3 + 3.0f * t2f + 3.0f * t + 1.0f) * (1.0f / 6.0f);
            float b3 = t3 * (1.0f / 6.0f);
            int j0 = m - 3;
            if (j0 >= 0     && j0 <= 10)     f2[q][1 + j0] = b0;
            if (j0 + 1 >= 0 && j0 + 1 <= 10) f2[q][2 + j0] = b1;
            if (j0 + 2 >= 0 && j0 + 2 <= 10) f2[q][3 + j0] = b2;
            if (j0 + 3 >= 0 && j0 + 3 <= 10) f2[q][4 + j0] = b3;
        }
    }
    __half2* base = reinterpret_cast<__half2*>(sBb + s_local * NFEAT * SB + pp);
    #pragma unroll
    for (int j = 0; j < NFEAT; j++)
        base[j * (SB / 2)] = __floats2half2_rn(f2[0][j], f2[1][j]);
}

// W chunk: 128 rows x 48 halves = 768 x 16B; 6 cp.async per producer thread.
__device__ __forceinline__ void issue_w_chunk(uint32_t sAb, int g, int t2) {
    const __half* src0 = g_W + g * KC;
    #pragma unroll
    for (int r = 0; r < 6; r++) {
        int i = r * 128 + t2;            // 0..767
        int row = i / 6, seg = i - row * 6;
        cp_async16(sAb + (uint32_t)(row * SA + seg * 8) * 2u,
                   src0 + (size_t)row * K_TOTAL + seg * 8);
    }
    cp_commit();
}

// ============================================================================
// Kernel 2: warp-specialized fused F-build + GEMM over one K-split.
// CTA = 128 channels x 64 pixels. Warps 0-7 MMA (32x32), 8-11 producers.
// ============================================================================
__global__ __launch_bounds__(NTHR, 2)
void fused_gemm_kernel(const float* __restrict__ x) {
    __shared__ __align__(16) __half sA[2][A_HALVES];  // 28672 B
    __shared__ __align__(16) __half sB[2][B_HALVES];  // 13824 B

    int tid  = threadIdx.x;
    int lane = tid & 31;
    int wid  = tid >> 5;

    int bid   = blockIdx.x;
    int split = bid >> 7;        // 0..3
    int ptile = bid & 127;
    int pg    = ptile * 64;
    int n_img = pg >> 10;
    int poff  = pg & 1023;
    int g0    = split * NIT_S;

    if (wid >= 8) {
        // ================= PRODUCER (warps 8-11) ========================
        int t2 = tid - 256;
        float v0, v1;
        feat_load(x, g0, t2, poff, n_img, v0, v1);   // stage-0 x loads
        for (int s = 0; s < NIT_S; s++) {
            int b = s & 1;
            if (s >= 2) bar_sync(BAR_EMPTY(b));
            issue_w_chunk(smem_u32(sA[b]), g0 + s, t2);
            feat_store(v0, v1, sB[b], t2);           // consume stage-s values
            if (s + 1 < NIT_S)                        // prefetch stage s+1
                feat_load(x, g0 + s + 1, t2, poff, n_img, v0, v1);
            cp_wait0();
            bar_arrive(BAR_FULL(b));
        }
        return;
    }

    // ==================== CONSUMER (warps 0-7, 32x32 tiles) =============
    int wm = wid & 3;            // rows wm*32
    int wn = wid >> 2;           // cols wn*32

    float acc[2][4][4];
    #pragma unroll
    for (int mi = 0; mi < 2; mi++)
        #pragma unroll
        for (int ni = 0; ni < 4; ni++)
            #pragma unroll
            for (int q = 0; q < 4; q++) acc[mi][ni][q] = 0.0f;

    int a_row_l = (lane & 7) + (lane & 8);
    int a_col_l = (lane >> 4) << 3;
    int b_row_l = lane & 15;
    int b_col_l = (lane >> 4) << 3;

    for (int it = 0; it < NIT_S; it++) {
        int b = it & 1;
        bar_sync(BAR_FULL(b));

        uint32_t abase = smem_u32(sA[b]);
        uint32_t bbase = smem_u32(sB[b]);
        #pragma unroll
        for (int ks = 0; ks < 3; ks++) {
            int kb = ks * 16;
            uint32_t afr[2][4], bfr[2][4];
            #pragma unroll
            for (int mi = 0; mi < 2; mi++) {
                int row = wm * 32 + mi * 16 + a_row_l;
                ldsm_x4(afr[mi], abase + (uint32_t)(row * SA + kb + a_col_l) * 2u);
            }
            #pragma unroll
            for (int nb = 0; nb < 2; nb++) {
                int krow = kb + b_row_l;
                int n0 = wn * 32 + nb * 16 + b_col_l;
                ldsm_x4_t(bfr[nb], bbase + (uint32_t)(krow * SB + n0) * 2u);
            }
            #pragma unroll
            for (int mi = 0; mi < 2; mi++)
                #pragma unroll
                for (int nb = 0; nb < 2; nb++) {
                    mma16816(acc[mi][nb * 2 + 0], afr[mi], bfr[nb] + 0);
                    mma16816(acc[mi][nb * 2 + 1], afr[mi], bfr[nb] + 2);
                }
        }

        if (it + 2 < NIT_S) bar_arrive(BAR_EMPTY(b));
    }

    // ---- epilogue: partial [128 x 64] f32 tile to g_P[split] ------------
    float* pb = g_P + (size_t)split * (OUT_CH * 8192) + pg;
    #pragma unroll
    for (int mi = 0; mi < 2; mi++) {
        #pragma unroll
        for (int ni = 0; ni < 4; ni++) {
            int c   = wm * 32 + mi * 16 + (lane >> 2);
            int col = wn * 32 + ni * 8 + (lane & 3) * 2;
            *reinterpret_cast<float2*>(pb + (size_t)c * 8192 + col) =
                make_float2(acc[mi][ni][0], acc[mi][ni][1]);
            *reinterpret_cast<float2*>(pb + (size_t)(c + 8) * 8192 + col) =
                make_float2(acc[mi][ni][2], acc[mi][ni][3]);
        }
    }
}

// ============================================================================
// Kernel 3: deterministic reduce of 4 K-split partials -> (N,C,H,W) output
// ============================================================================
__global__ void reduce_kernel(float* __restrict__ out) {
    int i4 = blockIdx.x * blockDim.x + threadIdx.x;   // 0..262143
    const float4* P = reinterpret_cast<const float4*>(g_P);
    const size_t S4 = (size_t)OUT_CH * 8192 / 4;      // per-split float4 stride
    float4 a = P[i4];
    float4 b = P[i4 + S4];
    float4 c4 = P[i4 + 2 * S4];
    float4 d = P[i4 + 3 * S4];
    float4 r = make_float4(a.x + b.x + c4.x + d.x, a.y + b.y + c4.y + d.y,
                           a.z + b.z + c4.z + d.z, a.w + b.w + c4.w + d.w);
    int i = i4 << 2;
    int c = i >> 13;                 // channel
    int p = i & 8191;                // global pixel
    int n = p >> 10;
    int idx = ((n * OUT_CH + c) << 10) + (p & 1023);
    *reinterpret_cast<float4*>(out + idx) = r;
}

// ============================================================================
// Host launcher. Inputs: x, knots (fixed uniform grid -> unused), coeff, bw, sw
// ============================================================================
extern "C" void kernel_launch(void* const* d_in, const int* in_sizes, int n_in,
                              void* d_out, int out_size) {
    const float* x     = (const float*)d_in[0];
    const float* coeff = (const float*)d_in[2];
    const float* bw    = (const float*)d_in[3];
    const float* sw    = (const float*)d_in[4];
    float* out = (float*)d_out;
    (void)in_sizes; (void)n_in; (void)out_size;

    build_w_kernel<<<(OUT_CH * K_TOTAL + 255) / 256, 256>>>(coeff, bw, sw);
    fused_gemm_kernel<<<NSPLIT * 128, NTHR>>>(x);
    reduce_kernel<<<1024, 256>>>(out);
}